// round 6
// baseline (speedup 1.0000x reference)
#include <cuda_runtime.h>
#include <cstdint>

// ---------------- problem constants ----------------
#define M_TOK   256
#define K_IN    4096
#define N_OUT   11008
#define QZ_COLS 1376

// ---------------- scratch (device globals) ----------------
__device__ int8_t g_P[(size_t)N_OUT * K_IN];   // [n][k] exact (w - z), int8
__device__ int8_t g_xa[M_TOK * K_IN];          // x hi digit
__device__ int8_t g_xb[M_TOK * K_IN];          // x lo digit
__device__ float  g_srow[M_TOK];               // per-row scale

// ---------------- split x into int8 digits, per-row scale ----------------
__global__ __launch_bounds__(256) void split_x8(const float* __restrict__ x)
{
    __shared__ float red[8];
    const int row = blockIdx.x, t = threadIdx.x;
    const float4* xr = (const float4*)(x + (size_t)row * K_IN);
    float4 v[4];
    float mx = 0.f;
#pragma unroll
    for (int i = 0; i < 4; i++) {
        v[i] = xr[t * 4 + i];
        mx = fmaxf(mx, fmaxf(fmaxf(fabsf(v[i].x), fabsf(v[i].y)),
                             fmaxf(fabsf(v[i].z), fabsf(v[i].w))));
    }
#pragma unroll
    for (int o = 16; o; o >>= 1) mx = fmaxf(mx, __shfl_xor_sync(~0u, mx, o));
    if ((t & 31) == 0) red[t >> 5] = mx;
    __syncthreads();
    float m2 = red[t & 7];
#pragma unroll
    for (int o = 4; o; o >>= 1) m2 = fmaxf(m2, __shfl_xor_sync(~0u, m2, o));
    mx = m2;
    if (t == 0) g_srow[row] = mx * (1.f / 127.f);
    const float inv = 127.f / mx;

    uint32_t wa[4], wb[4];
    const float* f = (const float*)v;
#pragma unroll
    for (int i = 0; i < 4; i++) {
        uint32_t pa = 0, pb = 0;
#pragma unroll
        for (int j = 0; j < 4; j++) {
            float q  = f[i * 4 + j] * inv;
            float af = rintf(q);
            float r  = q - af;                       // exact
            int a = (int)af;
            int b = (int)rintf(r * 128.f);           // in [-64, 64]
            pa |= (uint32_t)(a & 0xFF) << (8 * j);
            pb |= (uint32_t)(b & 0xFF) << (8 * j);
        }
        wa[i] = pa; wb[i] = pb;
    }
    size_t off = (size_t)row * K_IN + t * 16;
    *(uint4*)(g_xa + off) = make_uint4(wa[0], wa[1], wa[2], wa[3]);
    *(uint4*)(g_xb + off) = make_uint4(wb[0], wb[1], wb[2], wb[3]);
}

// ---------------- dequant: qweight -> g_P [n][k] int8 (w - z) ----------------
__global__ __launch_bounds__(256) void dequant_kernel(const int* __restrict__ qweight,
                                                      const int* __restrict__ qzeros)
{
    __shared__ unsigned sw[32 * 65];
    const int tid = threadIdx.x;
    const int n0  = blockIdx.x * 64;
    const int kr0 = blockIdx.y * 32;
#pragma unroll
    for (int j = 0; j < 8; j++) {
        int i = tid + j * 256;
        int kr = i >> 6, c = i & 63;
        sw[kr * 65 + c] = (unsigned)qweight[(size_t)(kr0 + kr) * N_OUT + n0 + c];
    }
    __syncthreads();

    const int c   = tid >> 2;
    const int sub = tid & 3;
    const int n   = n0 + c;
    const int kbase = kr0 * 8 + sub * 64;     // within one group of 128
    const int g   = kbase >> 7;

    unsigned zp = (unsigned)qzeros[(size_t)g * QZ_COLS + (n >> 3)];
    int z1 = (int)((zp >> ((n & 7) * 4)) & 0xF) + 1;

    uint32_t w[16];
#pragma unroll
    for (int r = 0; r < 8; r++) {
        unsigned p = sw[(sub * 8 + r) * 65 + c];
        uint32_t w0 = 0, w1 = 0;
#pragma unroll
        for (int j = 0; j < 4; j++) {
            w0 |= (uint32_t)((((int)(p >> (4 * j)) & 0xF) - z1) & 0xFF) << (8 * j);
            w1 |= (uint32_t)((((int)(p >> (4 * j + 16)) & 0xF) - z1) & 0xFF) << (8 * j);
        }
        w[r * 2] = w0; w[r * 2 + 1] = w1;
    }
    int8_t* dst = g_P + (size_t)n * K_IN + kbase;
#pragma unroll
    for (int q = 0; q < 4; q++)
        *(uint4*)(dst + q * 16) = make_uint4(w[q * 4], w[q * 4 + 1], w[q * 4 + 2], w[q * 4 + 3]);
}

// ---------------- GEMM: IMMA s8, CTA 64x64, warp 32x32, BK=64, 3-stage ----------------
#define ROWB      80          // 64 data bytes + 16 pad (conflict-free, 16B aligned)
#define A_DIG_OFF 5120        // 64*80
#define B_OFF     10240       // 2 digits of A
#define STG_B     15360       // (128 + 64) rows * 80
#define STAGES    3
#define SSC_OFF   (STAGES * STG_B)          // 46080
#define SMEM_DYN  (SSC_OFF + 32 * 64 * 4)   // 54272

__device__ __forceinline__ uint32_t s2u(const void* p) {
    uint32_t a;
    asm("{ .reg .u64 t; cvta.to.shared.u64 t, %1; cvt.u32.u64 %0, t; }" : "=r"(a) : "l"(p));
    return a;
}
__device__ __forceinline__ void cp16(uint32_t d, const void* s) {
    asm volatile("cp.async.cg.shared.global [%0], [%1], 16;" :: "r"(d), "l"(s));
}
__device__ __forceinline__ void ldsm4(uint32_t* r, uint32_t a) {
    asm volatile("ldmatrix.sync.aligned.m8n8.x4.shared.b16 {%0,%1,%2,%3}, [%4];"
                 : "=r"(r[0]), "=r"(r[1]), "=r"(r[2]), "=r"(r[3]) : "r"(a));
}
__device__ __forceinline__ void imma16832(int* c, const uint32_t* a, const uint32_t* b) {
    asm volatile("mma.sync.aligned.m16n8k32.row.col.s32.s8.s8.s32 "
                 "{%0,%1,%2,%3}, {%4,%5,%6,%7}, {%8,%9}, {%0,%1,%2,%3};"
                 : "+r"(c[0]), "+r"(c[1]), "+r"(c[2]), "+r"(c[3])
                 : "r"(a[0]), "r"(a[1]), "r"(a[2]), "r"(a[3]), "r"(b[0]), "r"(b[1]));
}

__global__ __launch_bounds__(128, 3)
void qlin_imma(const float* __restrict__ scales, const float* __restrict__ bias,
               float* __restrict__ out)
{
    extern __shared__ char smem[];
    const uint32_t sb = s2u(smem);
    float* sSc = (float*)(smem + SSC_OFF);   // [32 groups][64 cols]

    const int tid = threadIdx.x;
    const int l   = tid & 31;
    const int wid = tid >> 5;
    const int wm  = wid & 1;
    const int wn  = wid >> 1;
    const int m0  = blockIdx.x * 64;     // m fastest -> L2 reuse of P
    const int n0  = blockIdx.y * 64;

#pragma unroll
    for (int j = 0; j < 16; j++) {
        int idx = tid + j * 128;
        sSc[idx] = scales[(size_t)(idx >> 6) * N_OUT + n0 + (idx & 63)];
    }

    // cp.async fill mappings
    auto issue = [&](int st, int k0) {
        uint32_t base = sb + st * STG_B;
        if (k0 < K_IN) {
#pragma unroll
            for (int j = 0; j < 4; j++) {           // A: 2 digits x 64 rows x 4 chunks
                int idx = tid + j * 128;
                int dig = idx >> 8, rem = idx & 255;
                int row = rem >> 2, ch = rem & 3;
                const int8_t* src = (dig ? g_xb : g_xa) + (size_t)(m0 + row) * K_IN + k0 + ch * 16;
                cp16(base + dig * A_DIG_OFF + row * ROWB + ch * 16, src);
            }
#pragma unroll
            for (int j = 0; j < 2; j++) {           // B: 64 rows x 4 chunks
                int idx = tid + j * 128;
                int row = idx >> 2, ch = idx & 3;
                cp16(base + B_OFF + row * ROWB + ch * 16,
                     g_P + (size_t)(n0 + row) * K_IN + k0 + ch * 16);
            }
        }
        asm volatile("cp.async.commit_group;");
    };

    int   acc_a[2][4][4], acc_b[2][4][4];
    float acc_f[2][4][4];
#pragma unroll
    for (int mi = 0; mi < 2; mi++)
#pragma unroll
        for (int ni = 0; ni < 4; ni++)
#pragma unroll
            for (int q = 0; q < 4; q++) { acc_a[mi][ni][q] = 0; acc_b[mi][ni][q] = 0; acc_f[mi][ni][q] = 0.f; }

    issue(0, 0); issue(1, 64);

    // ldmatrix lane offsets
    const uint32_t aOff = (uint32_t)((wm * 32 + (l & 15)) * ROWB + (l >> 4) * 16);
    const uint32_t bOff = (uint32_t)(B_OFF + (wn * 32 + (l >> 4) * 8 + (l & 7)) * ROWB
                                     + ((l >> 3) & 1) * 16);

    int stage = 0;
    for (int it = 0; it < 64; it++) {
        asm volatile("cp.async.wait_group 1;" ::: "memory");
        __syncthreads();
        {
            int nst = stage + 2; if (nst >= STAGES) nst -= STAGES;
            issue(nst, (it + 2) * 64);
        }

        const uint32_t base = sb + stage * STG_B;
#pragma unroll
        for (int kk = 0; kk < 2; kk++) {
            uint32_t Aa[2][4], Ab[2][4], Bq[4][2];
#pragma unroll
            for (int mi = 0; mi < 2; mi++) {
                uint32_t aa = base + aOff + mi * (16 * ROWB) + kk * 32;
                ldsm4(Aa[mi], aa);
                ldsm4(Ab[mi], aa + A_DIG_OFF);
            }
#pragma unroll
            for (int bi = 0; bi < 2; bi++) {
                uint32_t t[4];
                ldsm4(t, base + bOff + bi * (16 * ROWB) + kk * 32);
                Bq[bi * 2][0] = t[0]; Bq[bi * 2][1] = t[1];
                Bq[bi * 2 + 1][0] = t[2]; Bq[bi * 2 + 1][1] = t[3];
            }
#pragma unroll
            for (int mi = 0; mi < 2; mi++)
#pragma unroll
                for (int ni = 0; ni < 4; ni++) {
                    imma16832(acc_a[mi][ni], Aa[mi], Bq[ni]);
                    imma16832(acc_b[mi][ni], Ab[mi], Bq[ni]);
                }
        }

        if (it & 1) {                   // group boundary: GROUP 128 = 2 iters of k64
            int g = it >> 1;
#pragma unroll
            for (int ni = 0; ni < 4; ni++) {
                float2 sc = *(float2*)&sSc[(g << 6) + wn * 32 + ni * 8 + ((l & 3) << 1)];
#pragma unroll
                for (int mi = 0; mi < 2; mi++)
#pragma unroll
                    for (int q = 0; q < 4; q++) {
                        float t = fmaf((float)acc_b[mi][ni][q], 0.0078125f,
                                       (float)acc_a[mi][ni][q]);
                        acc_f[mi][ni][q] = fmaf(t, (q & 1) ? sc.y : sc.x, acc_f[mi][ni][q]);
                        acc_a[mi][ni][q] = 0; acc_b[mi][ni][q] = 0;
                    }
            }
        }
        if (++stage >= STAGES) stage = 0;
    }

    // epilogue: apply s_row and bias
#pragma unroll
    for (int mi = 0; mi < 2; mi++) {
        int r0 = m0 + wm * 32 + mi * 16 + (l >> 2);
        float s0 = g_srow[r0], s1 = g_srow[r0 + 8];
#pragma unroll
        for (int ni = 0; ni < 4; ni++) {
            int col = n0 + wn * 32 + ni * 8 + ((l & 3) << 1);
            float b0 = bias[col], b1 = bias[col + 1];
            float2 v;
            v.x = acc_f[mi][ni][0] * s0 + b0;
            v.y = acc_f[mi][ni][1] * s0 + b1;
            *(float2*)&out[(size_t)r0 * N_OUT + col] = v;
            v.x = acc_f[mi][ni][2] * s1 + b0;
            v.y = acc_f[mi][ni][3] * s1 + b1;
            *(float2*)&out[(size_t)(r0 + 8) * N_OUT + col] = v;
        }
    }
}

// ---------------- launch ----------------
extern "C" void kernel_launch(void* const* d_in, const int* in_sizes, int n_in,
                              void* d_out, int out_size)
{
    const float* x       = (const float*)d_in[0];   // [256, 4096]
    const int*   qweight = (const int*)  d_in[1];   // [512, 11008]
    const int*   qzeros  = (const int*)  d_in[2];   // [32, 1376]
    const float* scales  = (const float*)d_in[3];   // [32, 11008]
    const float* bias    = (const float*)d_in[4];   // [11008]
    float*       out     = (float*)d_out;           // [256, 11008]

    static bool s_init = false;
    if (!s_init) {
        cudaFuncSetAttribute(qlin_imma, cudaFuncAttributeMaxDynamicSharedMemorySize, SMEM_DYN);
        s_init = true;
    }

    split_x8<<<M_TOK, 256>>>(x);
    dim3 dq_grid(N_OUT / 64, 512 / 32);             // (172, 16)
    dequant_kernel<<<dq_grid, 256>>>(qweight, qzeros);
    dim3 gm_grid(M_TOK / 64, N_OUT / 64);           // (4, 172): m fastest
    qlin_imma<<<gm_grid, 128, SMEM_DYN>>>(scales, bias, out);
}

// round 7
// speedup vs baseline: 1.6992x; 1.6992x over previous
#include <cuda_runtime.h>
#include <cuda_fp16.h>
#include <cstdint>

// ---------------- problem constants ----------------
#define M_TOK   256
#define K_IN    4096
#define N_OUT   11008
#define QZ_COLS 1376

// ---------------- scratch (device globals) ----------------
__device__ __half g_P[(size_t)N_OUT * K_IN];  // [n][k] fp16 (w - z) * s_group, k-permuted per 8
__device__ __half g_xh[M_TOK * K_IN];         // [m][k] fp16 rn(x), same k-permutation

// ---------------- split x: fp32 -> fp16, permute k within 8 ----------------
// permutation: positions (2p,2p+1) hold original (f[p], f[p+4])
__global__ __launch_bounds__(256) void split_x(const float* __restrict__ x)
{
    int t = blockIdx.x * 256 + threadIdx.x;          // 0..131071, 8 floats each
    const float4* x4 = (const float4*)x;
    float4 v0 = x4[(size_t)t * 2];
    float4 v1 = x4[(size_t)t * 2 + 1];
    float f[8] = {v0.x, v0.y, v0.z, v0.w, v1.x, v1.y, v1.z, v1.w};
    uint4 hi;
    uint32_t* hp = (uint32_t*)&hi;
#pragma unroll
    for (int p = 0; p < 4; p++) {
        __half2 hh = __halves2half2(__float2half_rn(f[p]), __float2half_rn(f[p + 4]));
        hp[p] = *(uint32_t*)&hh;
    }
    *(uint4*)(g_xh + (size_t)t * 8) = hi;
}

// ---------------- dequant: qweight -> g_P [n][k] fp16 (w - z) * s ----------------
__global__ __launch_bounds__(256) void dequant_kernel(const int* __restrict__ qweight,
                                                      const int* __restrict__ qzeros,
                                                      const float* __restrict__ scales)
{
    __shared__ unsigned sw[32 * 65];
    const int tid = threadIdx.x;
    const int n0  = blockIdx.x * 64;
    const int kr0 = blockIdx.y * 32;
#pragma unroll
    for (int j = 0; j < 8; j++) {
        int i = tid + j * 256;
        int kr = i >> 6, c = i & 63;
        sw[kr * 65 + c] = (unsigned)qweight[(size_t)(kr0 + kr) * N_OUT + n0 + c];
    }
    __syncthreads();

    const int c   = tid >> 2;
    const int sub = tid & 3;
    const int n   = n0 + c;
    const int kbase = kr0 * 8 + sub * 64;     // within one group of 128
    const int g   = kbase >> 7;

    unsigned zp = (unsigned)qzeros[(size_t)g * QZ_COLS + (n >> 3)];
    int z1 = (int)((zp >> ((n & 7) * 4)) & 0xF) + 1;
    unsigned zbu = 0x64006400u + (unsigned)((z1 << 16) | z1);
    __half2 zb = *(__half2*)&zbu;
    __half2 sh = __half2half2(__float2half_rn(scales[(size_t)g * N_OUT + n]));

    __half* dst = g_P + (size_t)n * K_IN + kbase;
#pragma unroll
    for (int r = 0; r < 8; r++) {
        unsigned p = sw[(sub * 8 + r) * 65 + c];
        uint4 o;
        uint32_t* op = (uint32_t*)&o;
#pragma unroll
        for (int q = 0; q < 4; q++) {
            unsigned t = (p >> (4 * q)) & 0x000F000Fu;   // nibbles (v_q, v_{q+4})
            unsigned h = t | 0x64006400u;                // halves 1024+v
            __half2 r2 = __hmul2(__hsub2(*(__half2*)&h, zb), sh);  // (w - z) * s
            op[q] = *(uint32_t*)&r2;
        }
        *(uint4*)(dst + r * 8) = o;
    }
}

// ---------------- GEMM: mma.sync fp16, BM=128 BN=128 BK=32, 3-stage cp.async ----------------
#define STAGES 3
#define ROWB   80          // 64 data bytes (32 halves) + 16 pad
#define B_OFF  10240       // 128 rows * 80
#define STG_B  20480       // A (128*80) + B (128*80)
#define SMEM_DYN (STAGES * STG_B)   // 61440 -> 2 CTAs/SM

__device__ __forceinline__ uint32_t s2u(const void* p) {
    uint32_t a;
    asm("{ .reg .u64 t; cvta.to.shared.u64 t, %1; cvt.u32.u64 %0, t; }" : "=r"(a) : "l"(p));
    return a;
}
__device__ __forceinline__ void cp16(uint32_t d, const void* s) {
    asm volatile("cp.async.cg.shared.global [%0], [%1], 16;" :: "r"(d), "l"(s));
}
__device__ __forceinline__ void ldsm4(uint32_t* r, uint32_t a) {
    asm volatile("ldmatrix.sync.aligned.m8n8.x4.shared.b16 {%0,%1,%2,%3}, [%4];"
                 : "=r"(r[0]), "=r"(r[1]), "=r"(r[2]), "=r"(r[3]) : "r"(a));
}
__device__ __forceinline__ void mma16816(float* c, const uint32_t* a, const uint32_t* b) {
    asm volatile("mma.sync.aligned.m16n8k16.row.col.f32.f16.f16.f32 "
                 "{%0,%1,%2,%3}, {%4,%5,%6,%7}, {%8,%9}, {%0,%1,%2,%3};"
                 : "+f"(c[0]), "+f"(c[1]), "+f"(c[2]), "+f"(c[3])
                 : "r"(a[0]), "r"(a[1]), "r"(a[2]), "r"(a[3]), "r"(b[0]), "r"(b[1]));
}

__global__ __launch_bounds__(256, 2)
void qlin_mma(const float* __restrict__ bias, float* __restrict__ out)
{
    extern __shared__ char smem[];
    const uint32_t sb = s2u(smem);

    const int tid = threadIdx.x;
    const int l   = tid & 31;
    const int wid = tid >> 5;
    const int wm  = wid & 3;            // 4 warps along m (32 rows each)
    const int wn  = wid >> 2;           // 2 warps along n (64 cols each)
    const int m0  = blockIdx.x * 128;   // m fastest -> adjacent CTAs share B slice in L2
    const int n0  = blockIdx.y * 128;

    // cp.async fill mapping: 16B chunks; A: 128 rows x 4 chunks, B: 128 rows x 4 chunks
    const int frow = tid >> 2, fch = (tid & 3) * 16;  // bytes within row
    const __half* gA = g_xh + (size_t)(m0 + frow) * K_IN + fch / 2;
    const __half* gB = g_P  + (size_t)(n0 + frow) * K_IN + fch / 2;
    const __half* gA2 = g_xh + (size_t)(m0 + 64 + frow) * K_IN + fch / 2;
    const __half* gB2 = g_P  + (size_t)(n0 + 64 + frow) * K_IN + fch / 2;
    const uint32_t dA  = (uint32_t)(frow * ROWB + fch);
    const uint32_t dB  = (uint32_t)(B_OFF + frow * ROWB + fch);
    const uint32_t dA2 = dA + 64 * ROWB;
    const uint32_t dB2 = dB + 64 * ROWB;

    auto issue = [&](int st, int k0) {
        uint32_t base = sb + st * STG_B;
        if (k0 < K_IN) {
            cp16(base + dA,  gA  + k0);
            cp16(base + dA2, gA2 + k0);
            cp16(base + dB,  gB  + k0);
            cp16(base + dB2, gB2 + k0);
        }
        asm volatile("cp.async.commit_group;");
    };

    float acc[2][8][4];
#pragma unroll
    for (int mi = 0; mi < 2; mi++)
#pragma unroll
        for (int ni = 0; ni < 8; ni++)
#pragma unroll
            for (int q = 0; q < 4; q++) acc[mi][ni][q] = 0.f;

    issue(0, 0); issue(1, 32);

    // ldmatrix lane offsets (bytes, relative to stage base)
    const uint32_t aLane = (uint32_t)((wm * 32 + (l & 15)) * ROWB + (l >> 4) * 16);
    const uint32_t bLane = (uint32_t)(B_OFF + (wn * 64 + (l >> 4) * 8 + (l & 7)) * ROWB
                                      + ((l >> 3) & 1) * 16);

    int stage = 0;
    for (int it = 0; it < 128; it++) {
        asm volatile("cp.async.wait_group 1;" ::: "memory");
        __syncthreads();
        {
            int nst = stage + 2; if (nst >= STAGES) nst -= STAGES;
            issue(nst, (it + 2) * 32);
        }

        const uint32_t base = sb + stage * STG_B;
#pragma unroll
        for (int kk = 0; kk < 2; kk++) {
            uint32_t Af[2][4], Bf[8][2];
#pragma unroll
            for (int mi = 0; mi < 2; mi++)
                ldsm4(Af[mi], base + aLane + mi * (16 * ROWB) + kk * 32);
#pragma unroll
            for (int bi = 0; bi < 4; bi++) {
                uint32_t t[4];
                ldsm4(t, base + bLane + bi * (16 * ROWB) + kk * 32);
                Bf[bi * 2][0] = t[0]; Bf[bi * 2][1] = t[1];
                Bf[bi * 2 + 1][0] = t[2]; Bf[bi * 2 + 1][1] = t[3];
            }
#pragma unroll
            for (int mi = 0; mi < 2; mi++)
#pragma unroll
                for (int ni = 0; ni < 8; ni++)
                    mma16816(acc[mi][ni], Af[mi], Bf[ni]);
        }
        if (++stage >= STAGES) stage = 0;
    }

    // epilogue: add bias, store
#pragma unroll
    for (int mi = 0; mi < 2; mi++) {
        int r0 = m0 + wm * 32 + mi * 16 + (l >> 2);
#pragma unroll
        for (int ni = 0; ni < 8; ni++) {
            int col = n0 + wn * 64 + ni * 8 + ((l & 3) << 1);
            float b0 = bias[col], b1 = bias[col + 1];
            float2 v;
            v.x = acc[mi][ni][0] + b0;
            v.y = acc[mi][ni][1] + b1;
            *(float2*)&out[(size_t)r0 * N_OUT + col] = v;
            v.x = acc[mi][ni][2] + b0;
            v.y = acc[mi][ni][3] + b1;
            *(float2*)&out[(size_t)(r0 + 8) * N_OUT + col] = v;
        }
    }
}

// ---------------- launch ----------------
extern "C" void kernel_launch(void* const* d_in, const int* in_sizes, int n_in,
                              void* d_out, int out_size)
{
    const float* x       = (const float*)d_in[0];   // [256, 4096]
    const int*   qweight = (const int*)  d_in[1];   // [512, 11008]
    const int*   qzeros  = (const int*)  d_in[2];   // [32, 1376]
    const float* scales  = (const float*)d_in[3];   // [32, 11008]
    const float* bias    = (const float*)d_in[4];   // [11008]
    float*       out     = (float*)d_out;           // [256, 11008]

    static bool s_init = false;
    if (!s_init) {
        cudaFuncSetAttribute(qlin_mma, cudaFuncAttributeMaxDynamicSharedMemorySize, SMEM_DYN);
        s_init = true;
    }

    split_x<<<512, 256>>>(x);
    dim3 dq_grid(N_OUT / 64, 512 / 32);             // (172, 16)
    dequant_kernel<<<dq_grid, 256>>>(qweight, qzeros, scales);
    dim3 gm_grid(M_TOK / 128, N_OUT / 128);         // (2, 86): m fastest, 172 CTAs = 1 wave
    qlin_mma<<<gm_grid, 256, SMEM_DYN>>>(bias, out);
}

// round 8
// speedup vs baseline: 2.4640x; 1.4501x over previous
#include <cuda_runtime.h>
#include <cuda_fp16.h>
#include <cstdint>

// ---------------- problem constants ----------------
#define M_TOK   256
#define K_IN    4096
#define N_OUT   11008
#define QZ_COLS 1376

// ---------------- scratch (device globals) ----------------
__device__ __half g_P[(size_t)N_OUT * K_IN];  // [n][k] fp16 (w - z) * s_group, k-permuted per 8
__device__ __half g_xh[M_TOK * K_IN];         // [m][k] fp16 rn(x), same k-permutation

// ---------------- split x: fp32 -> fp16, permute k within 8 ----------------
__global__ __launch_bounds__(256) void split_x(const float* __restrict__ x)
{
    int t = blockIdx.x * 256 + threadIdx.x;          // 0..131071, 8 floats each
    const float4* x4 = (const float4*)x;
    float4 v0 = x4[(size_t)t * 2];
    float4 v1 = x4[(size_t)t * 2 + 1];
    float f[8] = {v0.x, v0.y, v0.z, v0.w, v1.x, v1.y, v1.z, v1.w};
    uint4 hi;
    uint32_t* hp = (uint32_t*)&hi;
#pragma unroll
    for (int p = 0; p < 4; p++) {
        __half2 hh = __halves2half2(__float2half_rn(f[p]), __float2half_rn(f[p + 4]));
        hp[p] = *(uint32_t*)&hh;
    }
    *(uint4*)(g_xh + (size_t)t * 8) = hi;
}

// ---------------- dequant: qweight -> g_P [n][k] fp16 (w - z) * s ----------------
__global__ __launch_bounds__(256) void dequant_kernel(const int* __restrict__ qweight,
                                                      const int* __restrict__ qzeros,
                                                      const float* __restrict__ scales)
{
    __shared__ unsigned sw[32 * 65];
    const int tid = threadIdx.x;
    const int n0  = blockIdx.x * 64;
    const int kr0 = blockIdx.y * 32;
#pragma unroll
    for (int j = 0; j < 8; j++) {
        int i = tid + j * 256;
        int kr = i >> 6, c = i & 63;
        sw[kr * 65 + c] = (unsigned)qweight[(size_t)(kr0 + kr) * N_OUT + n0 + c];
    }
    __syncthreads();

    const int c   = tid >> 2;
    const int sub = tid & 3;
    const int n   = n0 + c;
    const int kbase = kr0 * 8 + sub * 64;
    const int g   = kbase >> 7;

    unsigned zp = (unsigned)qzeros[(size_t)g * QZ_COLS + (n >> 3)];
    int z1 = (int)((zp >> ((n & 7) * 4)) & 0xF) + 1;
    unsigned zbu = 0x64006400u + (unsigned)((z1 << 16) | z1);
    __half2 zb = *(__half2*)&zbu;
    __half2 sh = __half2half2(__float2half_rn(scales[(size_t)g * N_OUT + n]));

    __half* dst = g_P + (size_t)n * K_IN + kbase;
#pragma unroll
    for (int r = 0; r < 8; r++) {
        unsigned p = sw[(sub * 8 + r) * 65 + c];
        uint4 o;
        uint32_t* op = (uint32_t*)&o;
#pragma unroll
        for (int q = 0; q < 4; q++) {
            unsigned t = (p >> (4 * q)) & 0x000F000Fu;
            unsigned h = t | 0x64006400u;
            __half2 r2 = __hmul2(__hsub2(*(__half2*)&h, zb), sh);
            op[q] = *(uint32_t*)&r2;
        }
        *(uint4*)(dst + r * 8) = o;
    }
}

// ---------------- GEMM: mma.sync fp16, CTA 64x64, BK=32, 3-stage, 128 thr ----------------
#define STAGES 3
#define ROWB   80                 // 64 data bytes (32 halves) + 16 pad
#define B_OFF  (64 * ROWB)        // 5120
#define STG_B  (128 * ROWB)       // 10240: A 64 rows + B 64 rows
#define SMEM_DYN (STAGES * STG_B) // 30720 -> 4 CTAs/SM

__device__ __forceinline__ uint32_t s2u(const void* p) {
    uint32_t a;
    asm("{ .reg .u64 t; cvta.to.shared.u64 t, %1; cvt.u32.u64 %0, t; }" : "=r"(a) : "l"(p));
    return a;
}
__device__ __forceinline__ void cp16(uint32_t d, const void* s) {
    asm volatile("cp.async.cg.shared.global [%0], [%1], 16;" :: "r"(d), "l"(s));
}
__device__ __forceinline__ void ldsm4(uint32_t* r, uint32_t a) {
    asm volatile("ldmatrix.sync.aligned.m8n8.x4.shared.b16 {%0,%1,%2,%3}, [%4];"
                 : "=r"(r[0]), "=r"(r[1]), "=r"(r[2]), "=r"(r[3]) : "r"(a));
}
__device__ __forceinline__ void mma16816(float* c, const uint32_t* a, const uint32_t* b) {
    asm volatile("mma.sync.aligned.m16n8k16.row.col.f32.f16.f16.f32 "
                 "{%0,%1,%2,%3}, {%4,%5,%6,%7}, {%8,%9}, {%0,%1,%2,%3};"
                 : "+f"(c[0]), "+f"(c[1]), "+f"(c[2]), "+f"(c[3])
                 : "r"(a[0]), "r"(a[1]), "r"(a[2]), "r"(a[3]), "r"(b[0]), "r"(b[1]));
}

__global__ __launch_bounds__(128, 4)
void qlin_mma(const float* __restrict__ bias, float* __restrict__ out)
{
    extern __shared__ char smem[];
    const uint32_t sb = s2u(smem);

    const int tid = threadIdx.x;
    const int l   = tid & 31;
    const int wid = tid >> 5;
    const int wm  = wid & 1;            // 2 warps along m (32 rows each)
    const int wn  = wid >> 1;           // 2 warps along n (32 cols each)
    const int m0  = blockIdx.x * 64;    // m fastest -> adjacent CTAs share B slice in L2
    const int n0  = blockIdx.y * 64;

    // cp.async fill: thread covers rows arow, arow+32 of A and of B, chunk ch (16B)
    const int arow = tid >> 2;          // 0..31
    const int fch  = (tid & 3) * 16;    // bytes
    const __half* gA0 = g_xh + (size_t)(m0 + arow) * K_IN + fch / 2;
    const __half* gA1 = g_xh + (size_t)(m0 + arow + 32) * K_IN + fch / 2;
    const __half* gB0 = g_P  + (size_t)(n0 + arow) * K_IN + fch / 2;
    const __half* gB1 = g_P  + (size_t)(n0 + arow + 32) * K_IN + fch / 2;
    const uint32_t dA0 = (uint32_t)(arow * ROWB + fch);
    const uint32_t dA1 = dA0 + 32 * ROWB;
    const uint32_t dB0 = dA0 + B_OFF;
    const uint32_t dB1 = dA1 + B_OFF;

    auto issue = [&](int st, int k0) {
        uint32_t base = sb + st * STG_B;
        if (k0 < K_IN) {
            cp16(base + dA0, gA0 + k0);
            cp16(base + dA1, gA1 + k0);
            cp16(base + dB0, gB0 + k0);
            cp16(base + dB1, gB1 + k0);
        }
        asm volatile("cp.async.commit_group;");
    };

    float acc[2][4][4];
#pragma unroll
    for (int mi = 0; mi < 2; mi++)
#pragma unroll
        for (int ni = 0; ni < 4; ni++)
#pragma unroll
            for (int q = 0; q < 4; q++) acc[mi][ni][q] = 0.f;

    issue(0, 0); issue(1, 32);

    // ldmatrix lane offsets (bytes, relative to stage base)
    const uint32_t aLane = (uint32_t)((wm * 32 + (l & 15)) * ROWB + (l >> 4) * 16);
    const uint32_t bLane = (uint32_t)(B_OFF + (wn * 32 + (l >> 4) * 8 + (l & 7)) * ROWB
                                      + ((l >> 3) & 1) * 16);

    int stage = 0;
    for (int it = 0; it < 128; it++) {
        asm volatile("cp.async.wait_group 1;" ::: "memory");
        __syncthreads();
        {
            int nst = stage + 2; if (nst >= STAGES) nst -= STAGES;
            issue(nst, (it + 2) * 32);
        }

        const uint32_t base = sb + stage * STG_B;
#pragma unroll
        for (int kk = 0; kk < 2; kk++) {
            uint32_t Af[2][4], Bf[4][2];
#pragma unroll
            for (int mi = 0; mi < 2; mi++)
                ldsm4(Af[mi], base + aLane + mi * (16 * ROWB) + kk * 32);
#pragma unroll
            for (int bi = 0; bi < 2; bi++) {
                uint32_t t[4];
                ldsm4(t, base + bLane + bi * (16 * ROWB) + kk * 32);
                Bf[bi * 2][0] = t[0]; Bf[bi * 2][1] = t[1];
                Bf[bi * 2 + 1][0] = t[2]; Bf[bi * 2 + 1][1] = t[3];
            }
#pragma unroll
            for (int mi = 0; mi < 2; mi++)
#pragma unroll
                for (int ni = 0; ni < 4; ni++)
                    mma16816(acc[mi][ni], Af[mi], Bf[ni]);
        }
        if (++stage >= STAGES) stage = 0;
    }

    // epilogue: add bias, store
#pragma unroll
    for (int mi = 0; mi < 2; mi++) {
        int r0 = m0 + wm * 32 + mi * 16 + (l >> 2);
#pragma unroll
        for (int ni = 0; ni < 4; ni++) {
            int col = n0 + wn * 32 + ni * 8 + ((l & 3) << 1);
            float b0 = bias[col], b1 = bias[col + 1];
            float2 v;
            v.x = acc[mi][ni][0] + b0;
            v.y = acc[mi][ni][1] + b1;
            *(float2*)&out[(size_t)r0 * N_OUT + col] = v;
            v.x = acc[mi][ni][2] + b0;
            v.y = acc[mi][ni][3] + b1;
            *(float2*)&out[(size_t)(r0 + 8) * N_OUT + col] = v;
        }
    }
}

// ---------------- launch ----------------
extern "C" void kernel_launch(void* const* d_in, const int* in_sizes, int n_in,
                              void* d_out, int out_size)
{
    const float* x       = (const float*)d_in[0];   // [256, 4096]
    const int*   qweight = (const int*)  d_in[1];   // [512, 11008]
    const int*   qzeros  = (const int*)  d_in[2];   // [32, 1376]
    const float* scales  = (const float*)d_in[3];   // [32, 11008]
    const float* bias    = (const float*)d_in[4];   // [11008]
    float*       out     = (float*)d_out;           // [256, 11008]

    static bool s_init = false;
    if (!s_init) {
        cudaFuncSetAttribute(qlin_mma, cudaFuncAttributeMaxDynamicSharedMemorySize, SMEM_DYN);
        s_init = true;
    }

    split_x<<<512, 256>>>(x);
    dim3 dq_grid(N_OUT / 64, 512 / 32);             // (172, 16)
    dequant_kernel<<<dq_grid, 256>>>(qweight, qzeros, scales);
    dim3 gm_grid(M_TOK / 64, N_OUT / 64);           // (4, 172) = 688 tiles, m fastest
    qlin_mma<<<gm_grid, 128, SMEM_DYN>>>(bias, out);
}

// round 9
// speedup vs baseline: 3.8445x; 1.5603x over previous
#include <cuda_runtime.h>
#include <cuda_fp16.h>
#include <cstdint>

// ---------------- problem constants ----------------
#define M_TOK   256
#define K_IN    4096
#define N_OUT   11008
#define QZ_COLS 1376

// ---------------- scratch (device globals) ----------------
__device__ __half g_xh[M_TOK * K_IN];         // [m][k] fp16 rn(x), k-permuted per 8

// ---------------- split x: fp32 -> fp16, permute k within 8 ----------------
// permutation: positions (2p,2p+1) hold original (f[p], f[p+4])
__global__ __launch_bounds__(256) void split_x(const float* __restrict__ x)
{
    int t = blockIdx.x * 256 + threadIdx.x;          // 0..131071, 8 floats each
    const float4* x4 = (const float4*)x;
    float4 v0 = x4[(size_t)t * 2];
    float4 v1 = x4[(size_t)t * 2 + 1];
    float f[8] = {v0.x, v0.y, v0.z, v0.w, v1.x, v1.y, v1.z, v1.w};
    uint4 hi;
    uint32_t* hp = (uint32_t*)&hi;
#pragma unroll
    for (int p = 0; p < 4; p++) {
        __half2 hh = __halves2half2(__float2half_rn(f[p]), __float2half_rn(f[p + 4]));
        hp[p] = *(uint32_t*)&hh;
    }
    *(uint4*)(g_xh + (size_t)t * 8) = hi;
}

// ---------------- GEMM: fused dequant + mma.sync fp16, CTA 64x64, BK=32 ----------------
#define STAGES 3
#define ROWB   80                 // 64 data bytes (32 halves) + 16 pad
#define B_OFF  (64 * ROWB)        // 5120
#define STG_B  (128 * ROWB)       // 10240: A 64 rows + B 64 rows
#define SMEM_DYN (STAGES * STG_B) // 30720 -> 4 CTAs/SM
#define NBLK   128                // k-blocks of 32

__device__ __forceinline__ uint32_t s2u(const void* p) {
    uint32_t a;
    asm("{ .reg .u64 t; cvta.to.shared.u64 t, %1; cvt.u32.u64 %0, t; }" : "=r"(a) : "l"(p));
    return a;
}
__device__ __forceinline__ void cp16(uint32_t d, const void* s) {
    asm volatile("cp.async.cg.shared.global [%0], [%1], 16;" :: "r"(d), "l"(s));
}
__device__ __forceinline__ void ldsm4(uint32_t* r, uint32_t a) {
    asm volatile("ldmatrix.sync.aligned.m8n8.x4.shared.b16 {%0,%1,%2,%3}, [%4];"
                 : "=r"(r[0]), "=r"(r[1]), "=r"(r[2]), "=r"(r[3]) : "r"(a));
}
__device__ __forceinline__ void mma16816(float* c, const uint32_t* a, const uint32_t* b) {
    asm volatile("mma.sync.aligned.m16n8k16.row.col.f32.f16.f16.f32 "
                 "{%0,%1,%2,%3}, {%4,%5,%6,%7}, {%8,%9}, {%0,%1,%2,%3};"
                 : "+f"(c[0]), "+f"(c[1]), "+f"(c[2]), "+f"(c[3])
                 : "r"(a[0]), "r"(a[1]), "r"(a[2]), "r"(a[3]), "r"(b[0]), "r"(b[1]));
}

__global__ __launch_bounds__(128, 4)
void qlin_mma(const int* __restrict__ qweight,
              const int* __restrict__ qzeros,
              const float* __restrict__ scales,
              const float* __restrict__ bias,
              float* __restrict__ out)
{
    extern __shared__ char smem[];
    const uint32_t sb = s2u(smem);
    char* smem_p = smem;

    const int tid = threadIdx.x;
    const int l   = tid & 31;
    const int wid = tid >> 5;
    const int wm  = wid & 1;            // 2 warps along m (32 rows each)
    const int wn  = wid >> 1;           // 2 warps along n (32 cols each)
    const int m0  = blockIdx.x * 64;    // m fastest -> 4 m-CTAs share qweight slice in L2
    const int n0  = blockIdx.y * 64;

    // ---- A fill (cp.async): thread covers rows arow, arow+32, chunk fch ----
    const int arow = tid >> 2;
    const int fch  = (tid & 3) * 16;    // bytes
    const __half* gA0 = g_xh + (size_t)(m0 + arow) * K_IN + fch / 2;
    const __half* gA1 = g_xh + (size_t)(m0 + arow + 32) * K_IN + fch / 2;
    const uint32_t dA0 = (uint32_t)(arow * ROWB + fch);
    const uint32_t dA1 = dA0 + 32 * ROWB;

    // ---- B fill (fused dequant): thread handles packs (kr, nl) and (kr+2, nl) ----
    const int nl  = tid & 63;           // local n
    const int kr  = tid >> 6;           // 0 or 1 (second pack: kr+2)
    const int n   = n0 + nl;
    const int zshift = (n & 7) * 4;
    const int* qwp = qweight + (size_t)kr * N_OUT + n;   // + block*4*N_OUT
    const int* qzp = qzeros + (n >> 3);                   // + g*QZ_COLS
    const float* scp = scales + n;                        // + g*N_OUT

    // staged regs for block b (loaded 1 iter before STS)
    uint32_t spk0 = 0, spk1 = 0;
    __half2  szb = __half2half2(__float2half_rn(0.f));
    __half2  ssh = szb;

    auto ldB = [&](int b) {
        const int* q = qwp + (size_t)b * 4 * N_OUT;
        spk0 = (uint32_t)q[0];
        spk1 = (uint32_t)q[2 * N_OUT];
        int g = b >> 2;
        unsigned zp = (unsigned)qzp[(size_t)g * QZ_COLS];
        int z1 = (int)((zp >> zshift) & 0xF) + 1;
        unsigned zbu = 0x64006400u + (unsigned)((z1 << 16) | z1);
        szb = *(__half2*)&zbu;
        ssh = __half2half2(__float2half_rn(scp[(size_t)g * N_OUT]));
    };

    auto stB = [&](int st) {
        char* dst0 = smem_p + st * STG_B + B_OFF + nl * ROWB + kr * 16;
#pragma unroll
        for (int h = 0; h < 2; h++) {
            unsigned p = h ? spk1 : spk0;
            uint4 o;
            uint32_t* op = (uint32_t*)&o;
#pragma unroll
            for (int q = 0; q < 4; q++) {
                unsigned t = (p >> (4 * q)) & 0x000F000Fu;   // nibbles (v_q, v_{q+4})
                unsigned hh = t | 0x64006400u;               // halves 1024+v
                __half2 r2 = __hmul2(__hsub2(*(__half2*)&hh, szb), ssh);
                op[q] = *(uint32_t*)&r2;
            }
            *(uint4*)(dst0 + h * 32) = o;                    // kr and kr+2 chunks
        }
    };

    auto issueA = [&](int st, int b) {
        uint32_t base = sb + st * STG_B;
        int k0 = b * 32;
        cp16(base + dA0, gA0 + k0);
        cp16(base + dA1, gA1 + k0);
    };

    float acc[2][4][4];
#pragma unroll
    for (int mi = 0; mi < 2; mi++)
#pragma unroll
        for (int ni = 0; ni < 4; ni++)
#pragma unroll
            for (int q = 0; q < 4; q++) acc[mi][ni][q] = 0.f;

    // ---- prologue: fill stages 0,1; stage block 2 in regs ----
    ldB(0); stB(0); issueA(0, 0);
    asm volatile("cp.async.commit_group;");
    ldB(1); stB(1); issueA(1, 1);
    asm volatile("cp.async.commit_group;");
    ldB(2);
    __syncthreads();

    // ldmatrix lane offsets (bytes, relative to stage base)
    const uint32_t aLane = (uint32_t)((wm * 32 + (l & 15)) * ROWB + (l >> 4) * 16);
    const uint32_t bLane = (uint32_t)(B_OFF + (wn * 32 + (l >> 4) * 8 + (l & 7)) * ROWB
                                      + ((l >> 3) & 1) * 16);

    int stage = 0;
    for (int it = 0; it < NBLK; it++) {
        asm volatile("cp.async.wait_group 1;" ::: "memory");
        __syncthreads();

        // fill stage it+2 from staged regs; prefetch block it+3
        {
            int nst = stage + 2; if (nst >= STAGES) nst -= STAGES;
            if (it + 2 < NBLK) {
                stB(nst);
                issueA(nst, it + 2);
            }
            asm volatile("cp.async.commit_group;");
            if (it + 3 < NBLK) ldB(it + 3);
        }

        const uint32_t base = sb + stage * STG_B;
#pragma unroll
        for (int kk = 0; kk < 2; kk++) {
            uint32_t Af[2][4], Bf[4][2];
#pragma unroll
            for (int mi = 0; mi < 2; mi++)
                ldsm4(Af[mi], base + aLane + mi * (16 * ROWB) + kk * 32);
#pragma unroll
            for (int bi = 0; bi < 2; bi++) {
                uint32_t t[4];
                ldsm4(t, base + bLane + bi * (16 * ROWB) + kk * 32);
                Bf[bi * 2][0] = t[0]; Bf[bi * 2][1] = t[1];
                Bf[bi * 2 + 1][0] = t[2]; Bf[bi * 2 + 1][1] = t[3];
            }
#pragma unroll
            for (int mi = 0; mi < 2; mi++)
#pragma unroll
                for (int ni = 0; ni < 4; ni++)
                    mma16816(acc[mi][ni], Af[mi], Bf[ni]);
        }
        if (++stage >= STAGES) stage = 0;
    }

    // epilogue: add bias, store
#pragma unroll
    for (int mi = 0; mi < 2; mi++) {
        int r0 = m0 + wm * 32 + mi * 16 + (l >> 2);
#pragma unroll
        for (int ni = 0; ni < 4; ni++) {
            int col = n0 + wn * 32 + ni * 8 + ((l & 3) << 1);
            float b0 = bias[col], b1 = bias[col + 1];
            float2 v;
            v.x = acc[mi][ni][0] + b0;
            v.y = acc[mi][ni][1] + b1;
            *(float2*)&out[(size_t)r0 * N_OUT + col] = v;
            v.x = acc[mi][ni][2] + b0;
            v.y = acc[mi][ni][3] + b1;
            *(float2*)&out[(size_t)(r0 + 8) * N_OUT + col] = v;
        }
    }
}

// ---------------- launch ----------------
extern "C" void kernel_launch(void* const* d_in, const int* in_sizes, int n_in,
                              void* d_out, int out_size)
{
    const float* x       = (const float*)d_in[0];   // [256, 4096]
    const int*   qweight = (const int*)  d_in[1];   // [512, 11008]
    const int*   qzeros  = (const int*)  d_in[2];   // [32, 1376]
    const float* scales  = (const float*)d_in[3];   // [32, 11008]
    const float* bias    = (const float*)d_in[4];   // [11008]
    float*       out     = (float*)d_out;           // [256, 11008]

    static bool s_init = false;
    if (!s_init) {
        cudaFuncSetAttribute(qlin_mma, cudaFuncAttributeMaxDynamicSharedMemorySize, SMEM_DYN);
        s_init = true;
    }

    split_x<<<512, 256>>>(x);
    dim3 gm_grid(M_TOK / 64, N_OUT / 64);           // (4, 172) = 688 tiles, m fastest
    qlin_mma<<<gm_grid, 128, SMEM_DYN>>>(qweight, qzeros, scales, bias, out);
}